// round 2
// baseline (speedup 1.0000x reference)
#include <cuda_runtime.h>
#include <cstdint>
#include <math.h>

#define BATCH 256
#define TSTEP 512
#define INDIM 64
#define HID   256
#define NB    4          // batch rows per cluster
#define NCTA  (2*(BATCH/NB))   // 128 CTAs = 64 clusters of 2

// Scratch for the precomputed input projection, time-major: xw[t][b][h]
__device__ float g_xw[(size_t)TSTEP * BATCH * HID];

// Packed fp32x2 FMA (sm_100+): c += a*b elementwise on 2 floats
__device__ __forceinline__ void fma2(float2& c, float2 a, float2 b) {
    asm("fma.rn.f32x2 %0, %1, %2, %0;"
        : "+l"(reinterpret_cast<unsigned long long&>(c))
        : "l"(reinterpret_cast<unsigned long long&>(a)),
          "l"(reinterpret_cast<unsigned long long&>(b)));
}

// ---------------------------------------------------------------------------
// Kernel 1: xw[t][b][h] = x[b][t][:] . W_ih[h][:] + b_ih[h] + b_hh[h]
// Grid: (B, T/16), block 256 (thread = h). W_ih row in registers, x tile in smem.
// ---------------------------------------------------------------------------
__global__ __launch_bounds__(256) void xw_kernel(
    const float* __restrict__ x, const float* __restrict__ W_ih,
    const float* __restrict__ b_ih, const float* __restrict__ b_hh)
{
    __shared__ float xs[16 * INDIM];
    const int b  = blockIdx.x;
    const int t0 = blockIdx.y * 16;
    const int h  = threadIdx.x;

    // load 16x64 x-tile (contiguous 4KB) cooperatively
    ((float4*)xs)[h] = ((const float4*)(x + ((size_t)b * TSTEP + t0) * INDIM))[h];

    float2 w[32];
    {
        const float4* wr = (const float4*)(W_ih + (size_t)h * INDIM);
        #pragma unroll
        for (int q = 0; q < 16; q++) {
            float4 v = wr[q];
            w[2*q]   = make_float2(v.x, v.y);
            w[2*q+1] = make_float2(v.z, v.w);
        }
    }
    const float bias = b_ih[h] + b_hh[h];
    __syncthreads();

    #pragma unroll 4
    for (int tt = 0; tt < 16; tt++) {
        float2 acc = make_float2(0.f, 0.f);
        #pragma unroll
        for (int q = 0; q < 16; q++) {
            float4 xv = ((const float4*)(xs + tt * INDIM))[q];
            fma2(acc, w[2*q],   make_float2(xv.x, xv.y));
            fma2(acc, w[2*q+1], make_float2(xv.z, xv.w));
        }
        g_xw[((size_t)(t0 + tt) * BATCH + b) * HID + h] = acc.x + acc.y + bias;
    }
}

// ---------------------------------------------------------------------------
// Kernel 2: the scan. 2-CTA clusters; CTA rank r owns W_hh rows [128r,128r+128)
// in REGISTERS (thread (jj,kh) holds W_hh[128r+jj][128kh..+128) = 128 regs).
// Cluster owns NB=4 batch rows; h[NB][256] double-buffered in smem; per step
// each CTA computes its 128-output half for all 4 rows, tanh, writes slice to
// own + peer smem (DSMEM), then barrier.cluster. Final FC fused at the end.
// ---------------------------------------------------------------------------
__global__ void __cluster_dims__(2, 1, 1) __launch_bounds__(256, 1)
scan_kernel(const float* __restrict__ W_hh, const float* __restrict__ fc_W,
            const float* __restrict__ fc_b, float* __restrict__ out)
{
    __shared__ float hbuf[2][NB][HID];
    __shared__ float part[NB][2][128];
    __shared__ float fcw[HID];
    __shared__ float red[8];

    const int tid = threadIdx.x;
    const int jj  = tid & 127;
    const int kh  = tid >> 7;          // 0 or 1 : which k-half this thread owns
    uint32_t rank;
    asm("mov.u32 %0, %%cluster_ctarank;" : "=r"(rank));
    const int cid = blockIdx.x >> 1;   // cluster id
    const int b0  = cid * NB;          // first batch row of this cluster
    const int j   = (int)rank * 128 + jj;   // output column this thread produces

    // ---- load this thread's 128 W_hh weights into registers (as 64 float2)
    float2 w[64];
    {
        const float4* wr = (const float4*)(W_hh + (size_t)j * HID + kh * 128);
        #pragma unroll
        for (int q = 0; q < 32; q++) {
            float4 v = wr[q];
            w[2*q]   = make_float2(v.x, v.y);
            w[2*q+1] = make_float2(v.z, v.w);
        }
    }

    // ---- init h0 = 0 ; rank0 caches fc_W
    #pragma unroll
    for (int i = tid; i < NB * HID; i += 256) ((float*)hbuf[0])[i] = 0.f;
    if (rank == 0) fcw[tid] = fc_W[tid];

    asm volatile("barrier.cluster.arrive.aligned;" ::: "memory");
    asm volatile("barrier.cluster.wait.aligned;"   ::: "memory");

    const int bA = kh;        // combine: this thread finalizes rows bA and bB
    const int bB = kh + 2;
    const uint32_t peer = rank ^ 1;

    int cur = 0;
    for (int t = 0; t < TSTEP; t++) {
        const int nxt = cur ^ 1;
        // prefetch the xw additive terms used ~1000 cycles later in combine
        const float xw0 = g_xw[((size_t)t * BATCH + b0 + bA) * HID + j];
        const float xw1 = g_xw[((size_t)t * BATCH + b0 + bB) * HID + j];

        // ---- partial dot: acc[b] = sum over this thread's 128 k of W[j][k]*h[b][k]
        float2 a0 = make_float2(0.f, 0.f), a1 = a0, a2 = a0, a3 = a0;
        const float* hb = &hbuf[cur][0][kh * 128];
        #pragma unroll
        for (int q = 0; q < 32; q++) {
            float4 h0 = *(const float4*)(hb + 0 * HID + 4 * q);
            float4 h1 = *(const float4*)(hb + 1 * HID + 4 * q);
            float4 h2 = *(const float4*)(hb + 2 * HID + 4 * q);
            float4 h3 = *(const float4*)(hb + 3 * HID + 4 * q);
            fma2(a0, w[2*q],   make_float2(h0.x, h0.y));
            fma2(a0, w[2*q+1], make_float2(h0.z, h0.w));
            fma2(a1, w[2*q],   make_float2(h1.x, h1.y));
            fma2(a1, w[2*q+1], make_float2(h1.z, h1.w));
            fma2(a2, w[2*q],   make_float2(h2.x, h2.y));
            fma2(a2, w[2*q+1], make_float2(h2.z, h2.w));
            fma2(a3, w[2*q],   make_float2(h3.x, h3.y));
            fma2(a3, w[2*q+1], make_float2(h3.z, h3.w));
        }
        part[0][kh][jj] = a0.x + a0.y;
        part[1][kh][jj] = a1.x + a1.y;
        part[2][kh][jj] = a2.x + a2.y;
        part[3][kh][jj] = a3.x + a3.y;
        __syncthreads();

        // ---- combine halves + tanh ; each thread finalizes (bA,j) and (bB,j)
        float sA = part[bA][0][jj] + part[bA][1][jj] + xw0;
        float sB = part[bB][0][jj] + part[bB][1][jj] + xw1;
        float hA = tanhf(sA);
        float hB = tanhf(sB);
        hbuf[nxt][bA][j] = hA;
        hbuf[nxt][bB][j] = hB;

        // push our slice to the peer CTA's smem
        uint32_t la = (uint32_t)__cvta_generic_to_shared(&hbuf[nxt][bA][j]);
        uint32_t lb = (uint32_t)__cvta_generic_to_shared(&hbuf[nxt][bB][j]);
        uint32_t ra, rb;
        asm("mapa.shared::cluster.u32 %0, %1, %2;" : "=r"(ra) : "r"(la), "r"(peer));
        asm("mapa.shared::cluster.u32 %0, %1, %2;" : "=r"(rb) : "r"(lb), "r"(peer));
        asm volatile("st.shared::cluster.f32 [%0], %1;" :: "r"(ra), "f"(hA) : "memory");
        asm volatile("st.shared::cluster.f32 [%0], %1;" :: "r"(rb), "f"(hB) : "memory");

        // release our writes, acquire peer's
        asm volatile("barrier.cluster.arrive.aligned;" ::: "memory");
        asm volatile("barrier.cluster.wait.aligned;"   ::: "memory");
        cur = nxt;
    }

    // ---- fused FC: out[b] = fc_W . h_last[b] + fc_b   (rank-0 CTA has full h)
    if (rank == 0) {
        const int lane = tid & 31, wid = tid >> 5;
        #pragma unroll
        for (int b = 0; b < NB; b++) {
            float v = fcw[tid] * hbuf[cur][b][tid];
            #pragma unroll
            for (int o = 16; o; o >>= 1) v += __shfl_down_sync(0xffffffffu, v, o);
            if (lane == 0) red[wid] = v;
            __syncthreads();
            if (tid == 0) {
                float s = fc_b[0];
                #pragma unroll
                for (int ww = 0; ww < 8; ww++) s += red[ww];
                out[b0 + b] = s;
            }
            __syncthreads();
        }
    }
}

// ---------------------------------------------------------------------------
extern "C" void kernel_launch(void* const* d_in, const int* in_sizes, int n_in,
                              void* d_out, int out_size)
{
    const float* x    = (const float*)d_in[0];
    const float* W_ih = (const float*)d_in[1];
    const float* W_hh = (const float*)d_in[2];
    const float* b_ih = (const float*)d_in[3];
    const float* b_hh = (const float*)d_in[4];
    const float* fc_W = (const float*)d_in[5];
    const float* fc_b = (const float*)d_in[6];
    float* out = (float*)d_out;

    xw_kernel<<<dim3(BATCH, TSTEP / 16), 256>>>(x, W_ih, b_ih, b_hh);
    scan_kernel<<<NCTA, 256>>>(W_hh, fc_W, fc_b, out);
}

// round 3
// speedup vs baseline: 1.3572x; 1.3572x over previous
#include <cuda_runtime.h>
#include <cstdint>
#include <math.h>

#define BATCH 256
#define TSTEP 512
#define INDIM 64
#define HID   256
#define NB    4                  // batch rows per cluster
#define NCTA  (2*(BATCH/NB))     // 128 CTAs = 64 clusters of 2

// Scratch for the precomputed input projection, time-major: xw[t][b][h]
__device__ float g_xw[(size_t)TSTEP * BATCH * HID];

// Packed fp32x2 FMA (sm_100+): c += a*b elementwise on 2 floats
__device__ __forceinline__ void fma2(float2& c, float2 a, float2 b) {
    asm("fma.rn.f32x2 %0, %1, %2, %0;"
        : "+l"(reinterpret_cast<unsigned long long&>(c))
        : "l"(reinterpret_cast<unsigned long long&>(a)),
          "l"(reinterpret_cast<unsigned long long&>(b)));
}

// Fast tanh: 1 - 2/(exp(2x)+1).  Saturates correctly at +/-1 for |x| large.
__device__ __forceinline__ float ftanh(float x) {
    float e = __expf(x + x);               // MUFU ex2 based
    return 1.0f - __fdividef(2.0f, e + 1.0f);  // MUFU rcp based
}

// ---------------------------------------------------------------------------
// Kernel 1: xw[t][b][h] = x[b][t][:] . W_ih[h][:] + b_ih[h] + b_hh[h]
// Grid: (B, T/16), block 256 (thread = h). W_ih row in registers, x tile in smem.
// ---------------------------------------------------------------------------
__global__ __launch_bounds__(256) void xw_kernel(
    const float* __restrict__ x, const float* __restrict__ W_ih,
    const float* __restrict__ b_ih, const float* __restrict__ b_hh)
{
    __shared__ float xs[16 * INDIM];
    const int b  = blockIdx.x;
    const int t0 = blockIdx.y * 16;
    const int h  = threadIdx.x;

    ((float4*)xs)[h] = ((const float4*)(x + ((size_t)b * TSTEP + t0) * INDIM))[h];

    float2 w[32];
    {
        const float4* wr = (const float4*)(W_ih + (size_t)h * INDIM);
        #pragma unroll
        for (int q = 0; q < 16; q++) {
            float4 v = wr[q];
            w[2*q]   = make_float2(v.x, v.y);
            w[2*q+1] = make_float2(v.z, v.w);
        }
    }
    const float bias = b_ih[h] + b_hh[h];
    __syncthreads();

    #pragma unroll 4
    for (int tt = 0; tt < 16; tt++) {
        float2 acc = make_float2(0.f, 0.f);
        #pragma unroll
        for (int q = 0; q < 16; q++) {
            float4 xv = ((const float4*)(xs + tt * INDIM))[q];
            fma2(acc, w[2*q],   make_float2(xv.x, xv.y));
            fma2(acc, w[2*q+1], make_float2(xv.z, xv.w));
        }
        g_xw[((size_t)(t0 + tt) * BATCH + b) * HID + h] = acc.x + acc.y + bias;
    }
}

// ---------------------------------------------------------------------------
// Kernel 2: the scan. 2-CTA clusters; CTA rank r owns W_hh rows [128r,128r+128)
// in registers, k-split 4 ways: thread (jj, kq) holds W_hh[128r+jj][64kq..+64)
// = 64 regs. 512 threads/CTA -> 16 warps/SM for latency hiding.
// Cluster owns NB=4 batch rows; h[NB][256] double-buffered in smem; per step
// each CTA computes its 128-output half for all 4 rows, tanh, writes slice to
// own + peer smem (DSMEM), then barrier.cluster. Final FC fused at the end.
// ---------------------------------------------------------------------------
__global__ void __cluster_dims__(2, 1, 1) __launch_bounds__(512, 1)
scan_kernel(const float* __restrict__ W_hh, const float* __restrict__ fc_W,
            const float* __restrict__ fc_b, float* __restrict__ out)
{
    __shared__ float hbuf[2][NB][HID];   // 8 KB
    __shared__ float part[NB][4][128];   // 8 KB
    __shared__ float fcw[HID];
    __shared__ float red[16];

    const int tid = threadIdx.x;
    const int jj  = tid & 127;
    const int kq  = tid >> 7;            // 0..3 : which k-quarter this thread owns
    uint32_t rank;
    asm("mov.u32 %0, %%cluster_ctarank;" : "=r"(rank));
    const int cid = blockIdx.x >> 1;     // cluster id
    const int b0  = cid * NB;            // first batch row of this cluster
    const int j   = (int)rank * 128 + jj;

    // ---- this thread's 64 W_hh weights in registers (32 float2)
    float2 w[32];
    {
        const float4* wr = (const float4*)(W_hh + (size_t)j * HID + kq * 64);
        #pragma unroll
        for (int q = 0; q < 16; q++) {
            float4 v = wr[q];
            w[2*q]   = make_float2(v.x, v.y);
            w[2*q+1] = make_float2(v.z, v.w);
        }
    }

    // ---- init h0 = 0 ; rank0 caches fc_W
    for (int i = tid; i < NB * HID; i += 512) ((float*)hbuf[0])[i] = 0.f;
    if (rank == 0 && tid < HID) fcw[tid] = fc_W[tid];

    asm volatile("barrier.cluster.arrive.aligned;" ::: "memory");
    asm volatile("barrier.cluster.wait.aligned;"   ::: "memory");

    const uint32_t peer = rank ^ 1;

    int cur = 0;
    for (int t = 0; t < TSTEP; t++) {
        const int nxt = cur ^ 1;
        // prefetch the xw additive term used ~1000 cycles later in combine
        const float xw = g_xw[((size_t)t * BATCH + b0 + kq) * HID + j];

        // ---- partial dot: acc[b] = sum over this thread's 64 k of W[j][k]*h[b][k]
        float2 a0 = make_float2(0.f, 0.f), a1 = a0, a2 = a0, a3 = a0;
        const float* hb = &hbuf[cur][0][kq * 64];
        #pragma unroll
        for (int q = 0; q < 16; q++) {
            float4 h0 = *(const float4*)(hb + 0 * HID + 4 * q);
            float4 h1 = *(const float4*)(hb + 1 * HID + 4 * q);
            float4 h2 = *(const float4*)(hb + 2 * HID + 4 * q);
            float4 h3 = *(const float4*)(hb + 3 * HID + 4 * q);
            fma2(a0, w[2*q],   make_float2(h0.x, h0.y));
            fma2(a0, w[2*q+1], make_float2(h0.z, h0.w));
            fma2(a1, w[2*q],   make_float2(h1.x, h1.y));
            fma2(a1, w[2*q+1], make_float2(h1.z, h1.w));
            fma2(a2, w[2*q],   make_float2(h2.x, h2.y));
            fma2(a2, w[2*q+1], make_float2(h2.z, h2.w));
            fma2(a3, w[2*q],   make_float2(h3.x, h3.y));
            fma2(a3, w[2*q+1], make_float2(h3.z, h3.w));
        }
        part[0][kq][jj] = a0.x + a0.y;
        part[1][kq][jj] = a1.x + a1.y;
        part[2][kq][jj] = a2.x + a2.y;
        part[3][kq][jj] = a3.x + a3.y;
        __syncthreads();

        // ---- combine quarters + tanh ; thread finalizes (b=kq, j)
        float s = part[kq][0][jj] + part[kq][1][jj]
                + part[kq][2][jj] + part[kq][3][jj] + xw;
        float hv = ftanh(s);
        hbuf[nxt][kq][j] = hv;

        // push to the peer CTA's smem (DSMEM)
        uint32_t la = (uint32_t)__cvta_generic_to_shared(&hbuf[nxt][kq][j]);
        uint32_t ra;
        asm("mapa.shared::cluster.u32 %0, %1, %2;" : "=r"(ra) : "r"(la), "r"(peer));
        asm volatile("st.shared::cluster.f32 [%0], %1;" :: "r"(ra), "f"(hv) : "memory");

        // release our writes, acquire peer's
        asm volatile("barrier.cluster.arrive.aligned;" ::: "memory");
        asm volatile("barrier.cluster.wait.aligned;"   ::: "memory");
        cur = nxt;
    }

    // ---- fused FC: out[b] = fc_W . h_last[b] + fc_b   (rank-0 CTA has full h)
    if (rank == 0 && tid < HID) {
        const int lane = tid & 31, wid = tid >> 5;
        #pragma unroll
        for (int b = 0; b < NB; b++) {
            float v = fcw[tid] * hbuf[cur][b][tid];
            #pragma unroll
            for (int o = 16; o; o >>= 1) v += __shfl_down_sync(0xffffffffu, v, o);
            if (lane == 0) red[wid] = v;
            __syncthreads();
            if (tid == 0) {
                float sum = fc_b[0];
                #pragma unroll
                for (int ww = 0; ww < 8; ww++) sum += red[ww];
                out[b0 + b] = sum;
            }
            __syncthreads();
        }
    } else {
        // keep the barrier pattern uniform across the CTA for __syncthreads above
        if (rank == 0) {
            #pragma unroll
            for (int b = 0; b < NB; b++) { __syncthreads(); __syncthreads(); }
        }
    }
}

// ---------------------------------------------------------------------------
extern "C" void kernel_launch(void* const* d_in, const int* in_sizes, int n_in,
                              void* d_out, int out_size)
{
    const float* x    = (const float*)d_in[0];
    const float* W_ih = (const float*)d_in[1];
    const float* W_hh = (const float*)d_in[2];
    const float* b_ih = (const float*)d_in[3];
    const float* b_hh = (const float*)d_in[4];
    const float* fc_W = (const float*)d_in[5];
    const float* fc_b = (const float*)d_in[6];
    float* out = (float*)d_out;

    xw_kernel<<<dim3(BATCH, TSTEP / 16), 256>>>(x, W_ih, b_ih, b_hh);
    scan_kernel<<<NCTA, 512>>>(W_hh, fc_W, fc_b, out);
}